// round 1
// baseline (speedup 1.0000x reference)
#include <cuda_runtime.h>
#include <cuda_bf16.h>

// Problem constants (match reference: B=64, L=4096, D=256, fp32 in/out, ragged length)
#define BB 64
#define LL 4096
#define DD 256
#define SPLITS 32                 // L-chunks per batch -> 64*32 = 2048 CTAs
#define CHUNK (LL / SPLITS)       // 128 rows per CTA
#define D4 (DD / 4)               // 64 float4 per row

// length may arrive as int64 (reference declares int64) or int32 (JAX x64 off).
// Probe: interpreting the buffer as int64, element 0 is <= LL only in the true
// int64 layout; an int32 layout packs the next (>=1) length into the high word,
// making the probe >= 2^32.
__device__ __forceinline__ long long load_len(const void* lp, int b) {
    const long long probe = ((const long long*)lp)[0];
    if (probe >= 1 && probe <= (long long)LL)
        return ((const long long*)lp)[b];
    return (long long)((const int*)lp)[b];
}

__global__ void avg_zero_kernel(float* __restrict__ out) {
    out[blockIdx.x * DD + threadIdx.x] = 0.0f;
}

__global__ void __launch_bounds__(256) avg_partial_kernel(
    const float* __restrict__ in, const void* __restrict__ lenp,
    float* __restrict__ out)
{
    const int b     = blockIdx.x;       // batch
    const int chunk = blockIdx.y;       // L-chunk
    const int start = chunk * CHUNK;

    const long long lb = load_len(lenp, b);
    int end = start + CHUNK;
    if ((long long)end > lb) end = (int)lb;
    if (start >= end) return;           // uniform per block: safe before syncthreads

    const int tid = threadIdx.x;        // 256 threads
    const int d4  = tid & (D4 - 1);     // float4 column 0..63
    const int r   = tid >> 6;           // row-lane 0..3

    // base of this batch, as float4 rows of 64 elements
    const float4* __restrict__ base =
        (const float4*)(in + (size_t)b * LL * DD) + d4;

    float4 acc = make_float4(0.f, 0.f, 0.f, 0.f);

    int l = start + r;
    // main unrolled loop: 4 independent float4 loads in flight per thread
    #pragma unroll 1
    for (; l + 12 < end; l += 16) {
        float4 v0 = base[(size_t)(l     ) * D4];
        float4 v1 = base[(size_t)(l +  4) * D4];
        float4 v2 = base[(size_t)(l +  8) * D4];
        float4 v3 = base[(size_t)(l + 12) * D4];
        acc.x += v0.x + v1.x + v2.x + v3.x;
        acc.y += v0.y + v1.y + v2.y + v3.y;
        acc.z += v0.z + v1.z + v2.z + v3.z;
        acc.w += v0.w + v1.w + v2.w + v3.w;
    }
    for (; l < end; l += 4) {
        float4 v = base[(size_t)l * D4];
        acc.x += v.x; acc.y += v.y; acc.z += v.z; acc.w += v.w;
    }

    __shared__ float4 sm[256];
    sm[tid] = acc;
    __syncthreads();

    if (r == 0) {
        float4 a0 = sm[d4];
        float4 a1 = sm[d4 + 64];
        float4 a2 = sm[d4 + 128];
        float4 a3 = sm[d4 + 192];
        float sx = (a0.x + a1.x) + (a2.x + a3.x);
        float sy = (a0.y + a1.y) + (a2.y + a3.y);
        float sz = (a0.z + a1.z) + (a2.z + a3.z);
        float sw = (a0.w + a1.w) + (a2.w + a3.w);
        float* o = out + b * DD + d4 * 4;
        atomicAdd(o + 0, sx);
        atomicAdd(o + 1, sy);
        atomicAdd(o + 2, sz);
        atomicAdd(o + 3, sw);
    }
}

__global__ void avg_finalize_kernel(float* __restrict__ out,
                                    const void* __restrict__ lenp) {
    const int b = blockIdx.x;
    const float inv = 1.0f / (float)load_len(lenp, b);
    out[b * DD + threadIdx.x] *= inv;
}

extern "C" void kernel_launch(void* const* d_in, const int* in_sizes, int n_in,
                              void* d_out, int out_size) {
    const float* in   = (const float*)d_in[0];
    const void*  lenp = d_in[1];
    float* out = (float*)d_out;

    avg_zero_kernel<<<BB, DD>>>(out);
    avg_partial_kernel<<<dim3(BB, SPLITS), 256>>>(in, lenp, out);
    avg_finalize_kernel<<<BB, DD>>>(out, lenp);
}